// round 10
// baseline (speedup 1.0000x reference)
#include <cuda_runtime.h>
#include <math.h>
#include <stdint.h>

#define T_STEPS 1000
#define N_B     64
#define H_DIM   1024
#define C_DIM   256
#define G3      768

__device__ float g_xpT[(size_t)T_STEPS * G3 * N_B];   // [t][gate*256+c][n]

__device__ __forceinline__ float tf32_round(float f) {
    uint32_t r;
    asm("cvt.rna.tf32.f32 %0, %1;" : "=r"(r) : "f"(f));
    return __uint_as_float(r);
}
__device__ __forceinline__ void tf32_split(float x, float& hi, float& lo) {
    hi = tf32_round(x);
    lo = tf32_round(x - hi);
}

#define MMA_TF32(d, a, b)                                                       \
    asm volatile(                                                               \
        "mma.sync.aligned.m16n8k8.row.col.f32.tf32.tf32.f32 "                   \
        "{%0,%1,%2,%3}, {%4,%5,%6,%7}, {%8,%9}, {%0,%1,%2,%3};"                 \
        : "+f"(d[0]), "+f"(d[1]), "+f"(d[2]), "+f"(d[3])                        \
        : "r"(a[0]), "r"(a[1]), "r"(a[2]), "r"(a[3]), "r"(b[0]), "r"(b[1]))

#define BM 128
#define BN 128
#define BK 16
#define LDP 20

// ---------------------------------------------------------------------------
// Kernel 1: 3xTF32 tensor-core GEMM — VERBATIM round-9 passing version.
// ---------------------------------------------------------------------------
__global__ void __launch_bounds__(256) gemm_xp_tc(const float* __restrict__ A,
                                                  const float* __restrict__ W,
                                                  const float* __restrict__ bih)
{
    __shared__ float Ah[BM * LDP];
    __shared__ float Al[BM * LDP];
    __shared__ float Bh[BN * LDP];
    __shared__ float Bl[BN * LDP];

    const int tid  = threadIdx.x;
    const int m0   = blockIdx.y * BM;
    const int g0   = blockIdx.x * BN;
    const int warp = tid >> 5;
    const int lane = tid & 31;
    const int wm   = (warp & 1) * 64;
    const int wn   = (warp >> 1) * 32;
    const int lr_  = lane >> 2;
    const int lc_  = lane & 3;

    const int lrow = tid >> 1;
    const int lk   = (tid & 1) * 8;
    const float* Ag = A + (size_t)(m0 + lrow) * H_DIM + lk;
    const float* Wg = W + (size_t)(g0 + lrow) * H_DIM + lk;

    float4 ra0 = *(const float4*)(Ag);
    float4 ra1 = *(const float4*)(Ag + 4);
    float4 rb0 = *(const float4*)(Wg);
    float4 rb1 = *(const float4*)(Wg + 4);

    float acc[4][4][4];
    #pragma unroll
    for (int mi = 0; mi < 4; ++mi)
        #pragma unroll
        for (int ni = 0; ni < 4; ++ni)
            #pragma unroll
            for (int r = 0; r < 4; ++r) acc[mi][ni][r] = 0.f;

    for (int k0 = 0; k0 < H_DIM; k0 += BK) {
        __syncthreads();
        {
            float* aph = &Ah[lrow * LDP + lk];
            float* apl = &Al[lrow * LDP + lk];
            float av[8] = {ra0.x, ra0.y, ra0.z, ra0.w, ra1.x, ra1.y, ra1.z, ra1.w};
            #pragma unroll
            for (int i = 0; i < 8; ++i) tf32_split(av[i], aph[i], apl[i]);
            float* bph = &Bh[lrow * LDP + lk];
            float* bpl = &Bl[lrow * LDP + lk];
            float bv[8] = {rb0.x, rb0.y, rb0.z, rb0.w, rb1.x, rb1.y, rb1.z, rb1.w};
            #pragma unroll
            for (int i = 0; i < 8; ++i) tf32_split(bv[i], bph[i], bpl[i]);
        }
        __syncthreads();

        if (k0 + BK < H_DIM) {
            ra0 = *(const float4*)(Ag + k0 + BK);
            ra1 = *(const float4*)(Ag + k0 + BK + 4);
            rb0 = *(const float4*)(Wg + k0 + BK);
            rb1 = *(const float4*)(Wg + k0 + BK + 4);
        }

        #pragma unroll
        for (int kk = 0; kk < 2; ++kk) {
            const int kb = kk * 8;
            uint32_t afh[4][4], afl[4][4];
            #pragma unroll
            for (int mi = 0; mi < 4; ++mi) {
                int r = wm + mi * 16 + lr_;
                afh[mi][0] = __float_as_uint(Ah[r * LDP + kb + lc_]);
                afh[mi][1] = __float_as_uint(Ah[(r + 8) * LDP + kb + lc_]);
                afh[mi][2] = __float_as_uint(Ah[r * LDP + kb + lc_ + 4]);
                afh[mi][3] = __float_as_uint(Ah[(r + 8) * LDP + kb + lc_ + 4]);
                afl[mi][0] = __float_as_uint(Al[r * LDP + kb + lc_]);
                afl[mi][1] = __float_as_uint(Al[(r + 8) * LDP + kb + lc_]);
                afl[mi][2] = __float_as_uint(Al[r * LDP + kb + lc_ + 4]);
                afl[mi][3] = __float_as_uint(Al[(r + 8) * LDP + kb + lc_ + 4]);
            }
            uint32_t bfh[4][2], bfl[4][2];
            #pragma unroll
            for (int ni = 0; ni < 4; ++ni) {
                int cn = wn + ni * 8 + lr_;
                bfh[ni][0] = __float_as_uint(Bh[cn * LDP + kb + lc_]);
                bfh[ni][1] = __float_as_uint(Bh[cn * LDP + kb + lc_ + 4]);
                bfl[ni][0] = __float_as_uint(Bl[cn * LDP + kb + lc_]);
                bfl[ni][1] = __float_as_uint(Bl[cn * LDP + kb + lc_ + 4]);
            }
            #pragma unroll
            for (int mi = 0; mi < 4; ++mi)
                #pragma unroll
                for (int ni = 0; ni < 4; ++ni) {
                    MMA_TF32(acc[mi][ni], afl[mi], bfh[ni]);
                    MMA_TF32(acc[mi][ni], afh[mi], bfl[ni]);
                    MMA_TF32(acc[mi][ni], afh[mi], bfh[ni]);
                }
        }
    }

    #pragma unroll
    for (int mi = 0; mi < 4; ++mi) {
        int row = m0 + wm + mi * 16 + lr_;
        int t   = row >> 6;
        int n   = row & 63;
        #pragma unroll
        for (int ni = 0; ni < 4; ++ni) {
            int col = g0 + wn + ni * 8 + 2 * lc_;
            float bv0 = __ldg(&bih[col]);
            float bv1 = __ldg(&bih[col + 1]);
            float* p0 = &g_xpT[((size_t)t * G3 + col) * N_B];
            float* p1 = &g_xpT[((size_t)t * G3 + col + 1) * N_B];
            p0[n]     = acc[mi][ni][0] + bv0;
            p1[n]     = acc[mi][ni][1] + bv1;
            p0[n + 8] = acc[mi][ni][2] + bv0;
            p1[n + 8] = acc[mi][ni][3] + bv1;
        }
    }
}

// ---------------------------------------------------------------------------
// Kernel 2: cluster-parallel GRU scan with DSMEM h-exchange.
// 16 clusters x 8 CTAs x 256 threads; cluster owns rows 4cl..4cl+3, rank owns
// channels 32r..32r+31. Double-buffered h in smem: step t reads parity t&1,
// reducers broadcast hnew into every rank's parity (t&1)^1 buffer via
// mapa + st.shared::cluster; ONE cluster barrier per step (arrive=release,
// wait=acquire) orders the remote stores. Within a step remote writes touch
// only the write-parity buffer, readers only the read-parity buffer.
// out written directly in final [t][n][c] layout (coalesced per warp).
// ---------------------------------------------------------------------------
#define CL_CTAS 8
#define SCAN_THR 256
#define W_FLOATS   24576     // [3][256][32]
#define HBUF       1024      // one h buffer: [4][256]
#define RED_STRIDE 13        // padded (12 used) -> conflict-free reduce reads
#define RED_FLOATS (SCAN_THR * RED_STRIDE)
#define SCAN_SMEM_BYTES ((W_FLOATS + 2 * HBUF + RED_FLOATS) * 4)

#define CLUSTER_SYNC() do {                                          \
    asm volatile("barrier.cluster.arrive.aligned;" ::: "memory");    \
    asm volatile("barrier.cluster.wait.aligned;" ::: "memory");      \
} while (0)

__global__ void __launch_bounds__(SCAN_THR, 1) __cluster_dims__(CL_CTAS, 1, 1)
scan_cluster(const float* __restrict__ Whh,
             const float* __restrict__ bhh,
             float* __restrict__ out)
{
    extern __shared__ float sm[];
    float* W_s  = sm;                    // [3][256][32]  (g, k, ch)
    float* hbuf = sm + W_FLOATS;         // [2][4][256]   (parity, row, k)
    float* red  = hbuf + 2 * HBUF;       // [256][13]

    const int tid  = threadIdx.x;
    const int cl   = blockIdx.x >> 3;
    const int rank = blockIdx.x & 7;
    const int chl  = tid & 31;           // dot role: local channel
    const int ks   = tid >> 5;           // dot role: k-chunk 0..7
    const int k0   = ks * 32;

    const int rrow = tid >> 5;           // reducer role (tid<128): row 0..3
    const int rchl = tid & 31;
    const int c_g  = rank * 32 + rchl;
    const int n_g  = cl * 4 + rrow;

    // W slice: W_s[(g*256+k)*32 + chl] = Whh[(g*256 + rank*32 + chl)*256 + k]
    for (int idx = tid; idx < W_FLOATS; idx += SCAN_THR) {
        int lchl = idx & 31;
        int k    = (idx >> 5) & 255;
        int g    = idx >> 13;
        W_s[idx] = __ldg(&Whh[((size_t)(g * C_DIM + rank * 32 + lchl)) * C_DIM + k]);
    }
    #pragma unroll
    for (int i = 0; i < 2 * HBUF / SCAN_THR; ++i)
        hbuf[tid + i * SCAN_THR] = 0.f;

    float bhr = 0.f, bhz = 0.f, bhn = 0.f;
    if (tid < 128) {
        bhr = __ldg(&bhh[c_g]);
        bhz = __ldg(&bhh[C_DIM + c_g]);
        bhn = __ldg(&bhh[2 * C_DIM + c_g]);
    }
    __syncthreads();
    CLUSTER_SYNC();   // peers' h zero-init visible before any remote writes

    const uint32_t h_sh = (uint32_t)__cvta_generic_to_shared(hbuf);

    for (int t = 0; t < T_STEPS; ++t) {
        const float* hr = hbuf + (t & 1) * HBUF;    // read parity

        // xp gates for this step (reducers) — issues early, covered by the dot
        float xr = 0.f, xz = 0.f, xn = 0.f;
        if (tid < 128) {
            const float* xp = g_xpT + (size_t)t * (G3 * N_B);
            xr = __ldg(xp + (0 * C_DIM + c_g) * N_B + n_g);
            xz = __ldg(xp + (1 * C_DIM + c_g) * N_B + n_g);
            xn = __ldg(xp + (2 * C_DIM + c_g) * N_B + n_g);
        }

        // partial dot over own k-chunk
        float acc[4][3];
        #pragma unroll
        for (int rw = 0; rw < 4; ++rw)
            #pragma unroll
            for (int g = 0; g < 3; ++g) acc[rw][g] = 0.f;

        if (t > 0) {
            #pragma unroll
            for (int kk = 0; kk < 32; kk += 4) {
                const int k = k0 + kk;
                float4 h0 = *(const float4*)&hr[k];
                float4 h1 = *(const float4*)&hr[256 + k];
                float4 h2 = *(const float4*)&hr[512 + k];
                float4 h3 = *(const float4*)&hr[768 + k];
                const float hv[4][4] = {
                    {h0.x, h0.y, h0.z, h0.w},
                    {h1.x, h1.y, h1.z, h1.w},
                    {h2.x, h2.y, h2.z, h2.w},
                    {h3.x, h3.y, h3.z, h3.w}};
                #pragma unroll
                for (int g = 0; g < 3; ++g) {
                    const float* wp = &W_s[((g * 256 + k) << 5) + chl];
                    #pragma unroll
                    for (int q = 0; q < 4; ++q) {
                        float w = wp[q << 5];
                        acc[0][g] = fmaf(hv[0][q], w, acc[0][g]);
                        acc[1][g] = fmaf(hv[1][q], w, acc[1][g]);
                        acc[2][g] = fmaf(hv[2][q], w, acc[2][g]);
                        acc[3][g] = fmaf(hv[3][q], w, acc[3][g]);
                    }
                }
            }
        }

        {
            float* rp = &red[tid * RED_STRIDE];
            #pragma unroll
            for (int rw = 0; rw < 4; ++rw)
                #pragma unroll
                for (int g = 0; g < 3; ++g) rp[rw * 3 + g] = acc[rw][g];
        }
        __syncthreads();

        if (tid < 128) {
            float sr = 0.f, sz = 0.f, sn = 0.f;
            #pragma unroll
            for (int kq = 0; kq < 8; ++kq) {
                const float* rp = &red[((kq << 5) + rchl) * RED_STRIDE + rrow * 3];
                sr += rp[0];
                sz += rp[1];
                sn += rp[2];
            }
            float h_old = hr[rrow * 256 + c_g];

            float r  = 1.f / (1.f + expf(-(xr + sr + bhr)));
            float z  = 1.f / (1.f + expf(-(xz + sz + bhz)));
            float nt = tanhf(xn + r * (sn + bhn));
            float hnew = nt + z * (h_old - nt);

            // final-layout coalesced store: out[t][n][c]
            out[((size_t)t * N_B + n_g) * C_DIM + c_g] = hnew;

            // broadcast hnew into every rank's write-parity buffer (DSMEM)
            uint32_t laddr = h_sh + (uint32_t)((((t & 1) ^ 1) * HBUF + rrow * 256 + c_g) * 4);
            #pragma unroll
            for (int p = 0; p < CL_CTAS; ++p) {
                uint32_t raddr;
                asm volatile("mapa.shared::cluster.u32 %0, %1, %2;"
                             : "=r"(raddr) : "r"(laddr), "r"(p));
                asm volatile("st.shared::cluster.f32 [%0], %1;"
                             :: "r"(raddr), "f"(hnew) : "memory");
            }
        }

        CLUSTER_SYNC();   // arrive=release / wait=acquire orders the DSMEM stores
    }
}

// ---------------------------------------------------------------------------
// Kernel 3: log-softmax over c, in place on [t][n][c] (already final layout).
// One block per t, one warp per row (8 rows/warp), shuffle reductions.
// ---------------------------------------------------------------------------
__global__ void __launch_bounds__(256) logsoftmax_kernel(float* __restrict__ out)
{
    const int t    = blockIdx.x;
    const int w    = threadIdx.x >> 5;
    const int lane = threadIdx.x & 31;

    #pragma unroll
    for (int i = 0; i < 8; ++i) {
        const int n = w * 8 + i;
        float* row = out + ((size_t)t * N_B + n) * C_DIM;
        float4 a = *(const float4*)&row[lane * 4];
        float4 b = *(const float4*)&row[128 + lane * 4];

        float mx = fmaxf(fmaxf(fmaxf(a.x, a.y), fmaxf(a.z, a.w)),
                         fmaxf(fmaxf(b.x, b.y), fmaxf(b.z, b.w)));
        #pragma unroll
        for (int s = 16; s > 0; s >>= 1)
            mx = fmaxf(mx, __shfl_xor_sync(0xffffffffu, mx, s));

        float sum = expf(a.x - mx) + expf(a.y - mx) + expf(a.z - mx) + expf(a.w - mx)
                  + expf(b.x - mx) + expf(b.y - mx) + expf(b.z - mx) + expf(b.w - mx);
        #pragma unroll
        for (int s = 16; s > 0; s >>= 1)
            sum += __shfl_xor_sync(0xffffffffu, sum, s);

        float lse = mx + logf(sum);
        a.x -= lse; a.y -= lse; a.z -= lse; a.w -= lse;
        b.x -= lse; b.y -= lse; b.z -= lse; b.w -= lse;
        *(float4*)&row[lane * 4]       = a;
        *(float4*)&row[128 + lane * 4] = b;
    }
}

extern "C" void kernel_launch(void* const* d_in, const int* in_sizes, int n_in,
                              void* d_out, int out_size)
{
    const float* enc  = (const float*)d_in[0];
    const float* W_ih = (const float*)d_in[1];
    const float* W_hh = (const float*)d_in[2];
    const float* b_ih = (const float*)d_in[3];
    const float* b_hh = (const float*)d_in[4];
    float* out = (float*)d_out;

    cudaFuncSetAttribute(scan_cluster, cudaFuncAttributeMaxDynamicSharedMemorySize, SCAN_SMEM_BYTES);

    gemm_xp_tc<<<dim3(G3 / BN, (T_STEPS * N_B) / BM), 256>>>(enc, W_ih, b_ih);
    scan_cluster<<<128, SCAN_THR, SCAN_SMEM_BYTES>>>(W_hh, b_hh, out);
    logsoftmax_kernel<<<T_STEPS, 256>>>(out);
}

// round 11
// speedup vs baseline: 1.0880x; 1.0880x over previous
#include <cuda_runtime.h>
#include <math.h>
#include <stdint.h>

#define T_STEPS 1000
#define N_B     64
#define H_DIM   1024
#define C_DIM   256
#define G3      768

__device__ float g_xpT[(size_t)T_STEPS * G3 * N_B];   // [t][gate*256+c][n]
__device__ float g_hEx[16 * 1024];                     // per-cluster h exchange: [cl][row][c]

__device__ __forceinline__ float tf32_round(float f) {
    uint32_t r;
    asm("cvt.rna.tf32.f32 %0, %1;" : "=r"(r) : "f"(f));
    return __uint_as_float(r);
}
__device__ __forceinline__ void tf32_split(float x, float& hi, float& lo) {
    hi = tf32_round(x);
    lo = tf32_round(x - hi);
}

#define MMA_TF32(d, a, b)                                                       \
    asm volatile(                                                               \
        "mma.sync.aligned.m16n8k8.row.col.f32.tf32.tf32.f32 "                   \
        "{%0,%1,%2,%3}, {%4,%5,%6,%7}, {%8,%9}, {%0,%1,%2,%3};"                 \
        : "+f"(d[0]), "+f"(d[1]), "+f"(d[2]), "+f"(d[3])                        \
        : "r"(a[0]), "r"(a[1]), "r"(a[2]), "r"(a[3]), "r"(b[0]), "r"(b[1]))

#define BM 128
#define BN 128
#define BK 16
#define LDP 20
#define TILE_F (BM * LDP)          // 2560 floats per matrix per stage
#define STAGE_F (4 * TILE_F)       // Ah|Al|Bh|Bl
#define GEMM_SMEM_BYTES (2 * STAGE_F * 4)   // 81920

// ---------------------------------------------------------------------------
// Kernel 1: 3xTF32 tensor-core GEMM, double-buffered smem pipeline.
// Per k-iter: split-store NEXT tile into stage p^1 (overlaps MMA on stage p),
// prefetch tile k0+2BK into regs, MMA, ONE __syncthreads, flip p.
// ---------------------------------------------------------------------------
__global__ void __launch_bounds__(256) gemm_xp_tc(const float* __restrict__ A,
                                                  const float* __restrict__ W,
                                                  const float* __restrict__ bih)
{
    extern __shared__ float smg[];

    const int tid  = threadIdx.x;
    const int m0   = blockIdx.y * BM;
    const int g0   = blockIdx.x * BN;
    const int warp = tid >> 5;
    const int lane = tid & 31;
    const int wm   = (warp & 1) * 64;
    const int wn   = (warp >> 1) * 32;
    const int lr_  = lane >> 2;
    const int lc_  = lane & 3;

    const int lrow = tid >> 1;
    const int lk   = (tid & 1) * 8;
    const float* Ag = A + (size_t)(m0 + lrow) * H_DIM + lk;
    const float* Wg = W + (size_t)(g0 + lrow) * H_DIM + lk;

    float4 ra0, ra1, rb0, rb1;

    // split-store current regs into a stage
    auto store_split = [&](float* st) {
        float* aph = st + lrow * LDP + lk;              // Ah
        float* apl = aph + TILE_F;                      // Al
        float* bph = apl + TILE_F;                      // Bh
        float* bpl = bph + TILE_F;                      // Bl
        float av[8] = {ra0.x, ra0.y, ra0.z, ra0.w, ra1.x, ra1.y, ra1.z, ra1.w};
        float bv[8] = {rb0.x, rb0.y, rb0.z, rb0.w, rb1.x, rb1.y, rb1.z, rb1.w};
        #pragma unroll
        for (int i = 0; i < 8; ++i) tf32_split(av[i], aph[i], apl[i]);
        #pragma unroll
        for (int i = 0; i < 8; ++i) tf32_split(bv[i], bph[i], bpl[i]);
    };
    auto load_regs = [&](int k) {
        ra0 = *(const float4*)(Ag + k);
        ra1 = *(const float4*)(Ag + k + 4);
        rb0 = *(const float4*)(Wg + k);
        rb1 = *(const float4*)(Wg + k + 4);
    };

    float acc[4][4][4];
    #pragma unroll
    for (int mi = 0; mi < 4; ++mi)
        #pragma unroll
        for (int ni = 0; ni < 4; ++ni)
            #pragma unroll
            for (int r = 0; r < 4; ++r) acc[mi][ni][r] = 0.f;

    // prologue: tile0 -> stage0; tile1 -> regs
    load_regs(0);
    store_split(smg);
    if (BK < H_DIM) load_regs(BK);
    __syncthreads();

    int p = 0;
    for (int k0 = 0; k0 < H_DIM; k0 += BK) {
        float* cur = smg + p * STAGE_F;
        // stage the next tile while MMA below consumes the current one
        if (k0 + BK < H_DIM) {
            store_split(smg + (p ^ 1) * STAGE_F);
            if (k0 + 2 * BK < H_DIM) load_regs(k0 + 2 * BK);
        }

        const float* Ah = cur;
        const float* Al = cur + TILE_F;
        const float* Bh = cur + 2 * TILE_F;
        const float* Bl = cur + 3 * TILE_F;

        #pragma unroll
        for (int kk = 0; kk < 2; ++kk) {
            const int kb = kk * 8;
            uint32_t afh[4][4], afl[4][4];
            #pragma unroll
            for (int mi = 0; mi < 4; ++mi) {
                int r = wm + mi * 16 + lr_;
                afh[mi][0] = __float_as_uint(Ah[r * LDP + kb + lc_]);
                afh[mi][1] = __float_as_uint(Ah[(r + 8) * LDP + kb + lc_]);
                afh[mi][2] = __float_as_uint(Ah[r * LDP + kb + lc_ + 4]);
                afh[mi][3] = __float_as_uint(Ah[(r + 8) * LDP + kb + lc_ + 4]);
                afl[mi][0] = __float_as_uint(Al[r * LDP + kb + lc_]);
                afl[mi][1] = __float_as_uint(Al[(r + 8) * LDP + kb + lc_]);
                afl[mi][2] = __float_as_uint(Al[r * LDP + kb + lc_ + 4]);
                afl[mi][3] = __float_as_uint(Al[(r + 8) * LDP + kb + lc_ + 4]);
            }
            uint32_t bfh[4][2], bfl[4][2];
            #pragma unroll
            for (int ni = 0; ni < 4; ++ni) {
                int cn = wn + ni * 8 + lr_;
                bfh[ni][0] = __float_as_uint(Bh[cn * LDP + kb + lc_]);
                bfh[ni][1] = __float_as_uint(Bh[cn * LDP + kb + lc_ + 4]);
                bfl[ni][0] = __float_as_uint(Bl[cn * LDP + kb + lc_]);
                bfl[ni][1] = __float_as_uint(Bl[cn * LDP + kb + lc_ + 4]);
            }
            #pragma unroll
            for (int mi = 0; mi < 4; ++mi)
                #pragma unroll
                for (int ni = 0; ni < 4; ++ni) {
                    MMA_TF32(acc[mi][ni], afl[mi], bfh[ni]);
                    MMA_TF32(acc[mi][ni], afh[mi], bfl[ni]);
                    MMA_TF32(acc[mi][ni], afh[mi], bfh[ni]);
                }
        }
        __syncthreads();
        p ^= 1;
    }

    #pragma unroll
    for (int mi = 0; mi < 4; ++mi) {
        int row = m0 + wm + mi * 16 + lr_;
        int t   = row >> 6;
        int n   = row & 63;
        #pragma unroll
        for (int ni = 0; ni < 4; ++ni) {
            int col = g0 + wn + ni * 8 + 2 * lc_;
            float bv0 = __ldg(&bih[col]);
            float bv1 = __ldg(&bih[col + 1]);
            float* p0 = &g_xpT[((size_t)t * G3 + col) * N_B];
            float* p1 = &g_xpT[((size_t)t * G3 + col + 1) * N_B];
            p0[n]     = acc[mi][ni][0] + bv0;
            p1[n]     = acc[mi][ni][1] + bv1;
            p0[n + 8] = acc[mi][ni][2] + bv0;
            p1[n + 8] = acc[mi][ni][3] + bv1;
        }
    }
}

// ---------------------------------------------------------------------------
// Kernel 2: cluster-parallel GRU scan — r9 exchange (L2 g_hEx + cluster
// barrier + __ldcg reload), with r10's safe improvements:
//   - RED_STRIDE 13 (conflict-free reduce reads)
//   - coalesced out store in final [t][n][c] layout
//   - no __threadfence: barrier.cluster.arrive(release)/wait(acquire) at
//     cluster scope orders the g_hEx stores for same-cluster readers.
// ---------------------------------------------------------------------------
#define CL_CTAS 8
#define SCAN_THR 256
#define W_FLOATS   24576     // [3][256][32]
#define H_FLOATS   1024      // [4][256]
#define RED_STRIDE 13
#define RED_FLOATS (SCAN_THR * RED_STRIDE)
#define SCAN_SMEM_BYTES ((W_FLOATS + H_FLOATS + RED_FLOATS) * 4)

#define CLUSTER_SYNC() do {                                          \
    asm volatile("barrier.cluster.arrive.aligned;" ::: "memory");    \
    asm volatile("barrier.cluster.wait.aligned;" ::: "memory");      \
} while (0)

__global__ void __launch_bounds__(SCAN_THR, 1) __cluster_dims__(CL_CTAS, 1, 1)
scan_cluster(const float* __restrict__ Whh,
             const float* __restrict__ bhh,
             float* __restrict__ out)
{
    extern __shared__ float sm[];
    float* W_s = sm;                    // [3][256][32]  (g, k, ch)
    float* h_s = sm + W_FLOATS;         // [4][256]      (row, k)
    float* red = h_s + H_FLOATS;        // [256][13]

    const int tid  = threadIdx.x;
    const int cl   = blockIdx.x >> 3;
    const int rank = blockIdx.x & 7;
    const int chl  = tid & 31;
    const int ks   = tid >> 5;
    const int k0   = ks * 32;

    const int rrow = tid >> 5;          // reducer role (tid<128)
    const int rchl = tid & 31;
    const int c_g  = rank * 32 + rchl;
    const int n_g  = cl * 4 + rrow;

    for (int idx = tid; idx < W_FLOATS; idx += SCAN_THR) {
        int lchl = idx & 31;
        int k    = (idx >> 5) & 255;
        int g    = idx >> 13;
        W_s[idx] = __ldg(&Whh[((size_t)(g * C_DIM + rank * 32 + lchl)) * C_DIM + k]);
    }
    #pragma unroll
    for (int i = 0; i < H_FLOATS / SCAN_THR; ++i)
        h_s[tid + i * SCAN_THR] = 0.f;

    float bhr = 0.f, bhz = 0.f, bhn = 0.f;
    if (tid < 128) {
        bhr = __ldg(&bhh[c_g]);
        bhz = __ldg(&bhh[C_DIM + c_g]);
        bhn = __ldg(&bhh[2 * C_DIM + c_g]);
    }
    __syncthreads();

    for (int t = 0; t < T_STEPS; ++t) {
        float xr = 0.f, xz = 0.f, xn = 0.f;
        if (tid < 128) {
            const float* xp = g_xpT + (size_t)t * (G3 * N_B);
            xr = __ldg(xp + (0 * C_DIM + c_g) * N_B + n_g);
            xz = __ldg(xp + (1 * C_DIM + c_g) * N_B + n_g);
            xn = __ldg(xp + (2 * C_DIM + c_g) * N_B + n_g);
        }

        float acc[4][3];
        #pragma unroll
        for (int rw = 0; rw < 4; ++rw)
            #pragma unroll
            for (int g = 0; g < 3; ++g) acc[rw][g] = 0.f;

        if (t > 0) {
            #pragma unroll
            for (int kk = 0; kk < 32; kk += 4) {
                const int k = k0 + kk;
                float4 h0 = *(const float4*)&h_s[k];
                float4 h1 = *(const float4*)&h_s[256 + k];
                float4 h2 = *(const float4*)&h_s[512 + k];
                float4 h3 = *(const float4*)&h_s[768 + k];
                const float hv[4][4] = {
                    {h0.x, h0.y, h0.z, h0.w},
                    {h1.x, h1.y, h1.z, h1.w},
                    {h2.x, h2.y, h2.z, h2.w},
                    {h3.x, h3.y, h3.z, h3.w}};
                #pragma unroll
                for (int g = 0; g < 3; ++g) {
                    const float* wp = &W_s[((g * 256 + k) << 5) + chl];
                    #pragma unroll
                    for (int q = 0; q < 4; ++q) {
                        float w = wp[q << 5];
                        acc[0][g] = fmaf(hv[0][q], w, acc[0][g]);
                        acc[1][g] = fmaf(hv[1][q], w, acc[1][g]);
                        acc[2][g] = fmaf(hv[2][q], w, acc[2][g]);
                        acc[3][g] = fmaf(hv[3][q], w, acc[3][g]);
                    }
                }
            }
        }

        {
            float* rp = &red[tid * RED_STRIDE];
            #pragma unroll
            for (int rw = 0; rw < 4; ++rw)
                #pragma unroll
                for (int g = 0; g < 3; ++g) rp[rw * 3 + g] = acc[rw][g];
        }
        __syncthreads();

        if (tid < 128) {
            float sr = 0.f, sz = 0.f, sn = 0.f;
            #pragma unroll
            for (int kq = 0; kq < 8; ++kq) {
                const float* rp = &red[((kq << 5) + rchl) * RED_STRIDE + rrow * 3];
                sr += rp[0];
                sz += rp[1];
                sn += rp[2];
            }
            float h_old = h_s[rrow * 256 + c_g];

            float r  = 1.f / (1.f + expf(-(xr + sr + bhr)));
            float z  = 1.f / (1.f + expf(-(xz + sz + bhz)));
            float nt = tanhf(xn + r * (sn + bhn));
            float hnew = nt + z * (h_old - nt);

            __stcg(&g_hEx[cl * 1024 + rrow * 256 + c_g], hnew);
            // coalesced final-layout store
            out[((size_t)t * N_B + n_g) * C_DIM + c_g] = hnew;
        }

        // barrier.cluster.arrive has release semantics (cluster scope) — the
        // g_hEx stores above are ordered for same-cluster readers after wait.
        CLUSTER_SYNC();
        if (t < T_STEPS - 1) {
            #pragma unroll
            for (int i = 0; i < H_FLOATS / SCAN_THR; ++i)
                h_s[tid + i * SCAN_THR] = __ldcg(&g_hEx[cl * 1024 + tid + i * SCAN_THR]);
            __syncthreads();
        }
    }
}

// ---------------------------------------------------------------------------
// Kernel 3: log-softmax over c, in place on [t][n][c]. Warp per row.
// ---------------------------------------------------------------------------
__global__ void __launch_bounds__(256) logsoftmax_kernel(float* __restrict__ out)
{
    const int t    = blockIdx.x;
    const int w    = threadIdx.x >> 5;
    const int lane = threadIdx.x & 31;

    #pragma unroll
    for (int i = 0; i < 8; ++i) {
        const int n = w * 8 + i;
        float* row = out + ((size_t)t * N_B + n) * C_DIM;
        float4 a = *(const float4*)&row[lane * 4];
        float4 b = *(const float4*)&row[128 + lane * 4];

        float mx = fmaxf(fmaxf(fmaxf(a.x, a.y), fmaxf(a.z, a.w)),
                         fmaxf(fmaxf(b.x, b.y), fmaxf(b.z, b.w)));
        #pragma unroll
        for (int s = 16; s > 0; s >>= 1)
            mx = fmaxf(mx, __shfl_xor_sync(0xffffffffu, mx, s));

        float sum = expf(a.x - mx) + expf(a.y - mx) + expf(a.z - mx) + expf(a.w - mx)
                  + expf(b.x - mx) + expf(b.y - mx) + expf(b.z - mx) + expf(b.w - mx);
        #pragma unroll
        for (int s = 16; s > 0; s >>= 1)
            sum += __shfl_xor_sync(0xffffffffu, sum, s);

        float lse = mx + logf(sum);
        a.x -= lse; a.y -= lse; a.z -= lse; a.w -= lse;
        b.x -= lse; b.y -= lse; b.z -= lse; b.w -= lse;
        *(float4*)&row[lane * 4]       = a;
        *(float4*)&row[128 + lane * 4] = b;
    }
}

extern "C" void kernel_launch(void* const* d_in, const int* in_sizes, int n_in,
                              void* d_out, int out_size)
{
    const float* enc  = (const float*)d_in[0];
    const float* W_ih = (const float*)d_in[1];
    const float* W_hh = (const float*)d_in[2];
    const float* b_ih = (const float*)d_in[3];
    const float* b_hh = (const float*)d_in[4];
    float* out = (float*)d_out;

    cudaFuncSetAttribute(gemm_xp_tc, cudaFuncAttributeMaxDynamicSharedMemorySize, GEMM_SMEM_BYTES);
    cudaFuncSetAttribute(scan_cluster, cudaFuncAttributeMaxDynamicSharedMemorySize, SCAN_SMEM_BYTES);

    gemm_xp_tc<<<dim3(G3 / BN, (T_STEPS * N_B) / BM), 256, GEMM_SMEM_BYTES>>>(enc, W_ih, b_ih);
    scan_cluster<<<128, SCAN_THR, SCAN_SMEM_BYTES>>>(W_hh, b_hh, out);
    logsoftmax_kernel<<<T_STEPS, 256>>>(out);
}